// round 6
// baseline (speedup 1.0000x reference)
#include <cuda_runtime.h>

#define HWD   256
#define HW2   65536            // HWD*HWD
#define NB    8
#define NC    64
#define NPIX  (NB*HW2)         // 524288
#define HW24  16384            // HW2/4
#define NCHUNK NB              // 1 batch per chunk: 33.5 MB of x per chunk

// Scratch (static device globals — allocation-free)
__device__ float g_n1[NPIX];
__device__ float g_n2[NPIX];
__device__ float g_r1[NPIX];

// ---------------------------------------------------------------------------
// K1 (per batch): per-pixel channel L1 norms of x1 and x2.
// 8-way channel split within a block (32 pixel-quads x 8 groups of 8 ch),
// smem combine -> grid stays at 512 CTAs per chunk. Fully unrolled loop.
// Default-cached reads so the chunk persists in L2 for K3.
// ---------------------------------------------------------------------------
__global__ __launch_bounds__(256) void k_norm(const float4* __restrict__ x1,
                                              const float4* __restrict__ x2,
                                              int b) {
    __shared__ float4 sm1[8][32];
    __shared__ float4 sm2[8][32];
    int t = threadIdx.x;
    int p = t & 31;                  // pixel-quad within block
    int g = t >> 5;                  // channel group 0..7
    int hw4 = blockIdx.x * 32 + p;   // [0, HW24)
    size_t base = ((size_t)b * NC + g * 8) * HW24 + hw4;
    const float4* p1 = x1 + base;
    const float4* p2 = x2 + base;

    float4 s1 = make_float4(0.f, 0.f, 0.f, 0.f);
    float4 s2 = make_float4(0.f, 0.f, 0.f, 0.f);
#pragma unroll
    for (int c = 0; c < 8; ++c) {
        float4 a = p1[(size_t)c * HW24];
        float4 d = p2[(size_t)c * HW24];
        s1.x += fabsf(a.x); s1.y += fabsf(a.y); s1.z += fabsf(a.z); s1.w += fabsf(a.w);
        s2.x += fabsf(d.x); s2.y += fabsf(d.y); s2.z += fabsf(d.z); s2.w += fabsf(d.w);
    }
    sm1[g][p] = s1;
    sm2[g][p] = s2;
    __syncthreads();

    if (t < 32) {
        float4 o = make_float4(0.f, 0.f, 0.f, 0.f);
#pragma unroll
        for (int k = 0; k < 8; ++k) {
            float4 v = sm1[k][t];
            o.x += v.x; o.y += v.y; o.z += v.z; o.w += v.w;
        }
        reinterpret_cast<float4*>(g_n1)[b * HW24 + blockIdx.x * 32 + t] = o;
    } else if (t < 64) {
        int tt = t - 32;
        float4 o = make_float4(0.f, 0.f, 0.f, 0.f);
#pragma unroll
        for (int k = 0; k < 8; ++k) {
            float4 v = sm2[k][tt];
            o.x += v.x; o.y += v.y; o.z += v.z; o.w += v.w;
        }
        reinterpret_cast<float4*>(g_n2)[b * HW24 + blockIdx.x * 32 + tt] = o;
    }
}

// ---------------------------------------------------------------------------
// K2 (per batch): 3x3 conv (pad 1) + bias on n1/n2, write r1 = c1/(c1+c2).
// n arrays are L2-resident (0.5 MB per batch).
// ---------------------------------------------------------------------------
__global__ __launch_bounds__(256) void k_conv_ratio(const float* __restrict__ w,
                                                    const float* __restrict__ bias,
                                                    int b) {
    int hw = blockIdx.x * blockDim.x + threadIdx.x;   // [0, HW2)
    if (hw >= HW2) return;
    int y  = hw >> 8;
    int x  = hw & (HWD - 1);

    float w00 = __ldg(w+0), w01 = __ldg(w+1), w02 = __ldg(w+2);
    float w10 = __ldg(w+3), w11 = __ldg(w+4), w12 = __ldg(w+5);
    float w20 = __ldg(w+6), w21 = __ldg(w+7), w22 = __ldg(w+8);
    float bv  = __ldg(bias);

    const float* n1 = g_n1 + b * HW2;
    const float* n2 = g_n2 + b * HW2;

    float c1 = 0.f, c2 = 0.f;
    bool ym = (y > 0), yp = (y < HWD - 1);
    bool xm = (x > 0), xp = (x < HWD - 1);
    int r0 = (y - 1) * HWD, r1r = y * HWD, r2r = (y + 1) * HWD;

    if (ym) {
        if (xm) { c1 += w00 * n1[r0 + x - 1]; c2 += w00 * n2[r0 + x - 1]; }
                  c1 += w01 * n1[r0 + x    ]; c2 += w01 * n2[r0 + x    ];
        if (xp) { c1 += w02 * n1[r0 + x + 1]; c2 += w02 * n2[r0 + x + 1]; }
    }
    if (xm) { c1 += w10 * n1[r1r + x - 1]; c2 += w10 * n2[r1r + x - 1]; }
              c1 += w11 * n1[r1r + x    ]; c2 += w11 * n2[r1r + x    ];
    if (xp) { c1 += w12 * n1[r1r + x + 1]; c2 += w12 * n2[r1r + x + 1]; }
    if (yp) {
        if (xm) { c1 += w20 * n1[r2r + x - 1]; c2 += w20 * n2[r2r + x - 1]; }
                  c1 += w21 * n1[r2r + x    ]; c2 += w21 * n2[r2r + x    ];
        if (xp) { c1 += w22 * n1[r2r + x + 1]; c2 += w22 * n2[r2r + x + 1]; }
    }
    c1 += bv;
    c2 += bv;
    g_r1[b * HW2 + hw] = c1 / (c1 + c2);
}

// ---------------------------------------------------------------------------
// K3 (per batch): out = x1*r1 + x2*(1-r1).
// Thread owns one pixel-quad x one 8-channel group (512 CTAs): r1 loaded
// ONCE, x loads last-use (__ldcs, evict-first — they are dead after this),
// out stores streaming (__stcs) to limit L2 pollution.
// ---------------------------------------------------------------------------
__global__ __launch_bounds__(256) void k_blend(const float4* __restrict__ x1,
                                               const float4* __restrict__ x2,
                                               float4* __restrict__ out,
                                               int b) {
    int i = blockIdx.x * blockDim.x + threadIdx.x;   // [0, 8*HW24)
    int q = i & (HW24 - 1);      // pixel-quad
    int g = i >> 14;             // channel group 0..7

    float4 r1 = __ldg(&reinterpret_cast<const float4*>(g_r1)[b * HW24 + q]);
    float4 r2 = make_float4(1.f - r1.x, 1.f - r1.y, 1.f - r1.z, 1.f - r1.w);

    size_t base = ((size_t)b * NC + g * 8) * HW24 + q;
#pragma unroll
    for (int c = 0; c < 8; ++c) {
        float4 a = __ldcs(x1 + base + (size_t)c * HW24);
        float4 d = __ldcs(x2 + base + (size_t)c * HW24);
        float4 o;
        o.x = a.x * r1.x + d.x * r2.x;
        o.y = a.y * r1.y + d.y * r2.y;
        o.z = a.z * r1.z + d.z * r2.z;
        o.w = a.w * r1.w + d.w * r2.w;
        __stcs(out + base + (size_t)c * HW24, o);
    }
}

// ---------------------------------------------------------------------------
// Pipelined launch:
//   main (captured) stream: pure back-to-back norms (keeps DRAM saturated)
//   side stream: wait(norm_c) -> conv_c -> blend_c  (consumes chunk c from L2
//   while norm_{c+1} streams in chunk c+1)
// Host-side stream/event resources created once; no device memory.
// ---------------------------------------------------------------------------
struct PipeRes {
    cudaStream_t s2;
    cudaEvent_t  evNorm[NCHUNK];
    cudaEvent_t  evBlendLast;
    PipeRes() {
        cudaStreamCreateWithFlags(&s2, cudaStreamNonBlocking);
        for (int c = 0; c < NCHUNK; ++c)
            cudaEventCreateWithFlags(&evNorm[c], cudaEventDisableTiming);
        cudaEventCreateWithFlags(&evBlendLast, cudaEventDisableTiming);
    }
};

extern "C" void kernel_launch(void* const* d_in, const int* in_sizes, int n_in,
                              void* d_out, int out_size) {
    static PipeRes R;   // created on first (correctness) call, before capture

    const float4* x1 = (const float4*)d_in[0];
    const float4* x2 = (const float4*)d_in[1];
    const float*  w  = (const float*)d_in[2];
    const float*  bv = (const float*)d_in[3];
    float4* out = (float4*)d_out;

    for (int b = 0; b < NCHUNK; ++b) {
        // producer: norm for batch b on the captured stream
        k_norm<<<HW24 / 32, 256, 0, 0>>>(x1, x2, b);
        cudaEventRecord(R.evNorm[b], 0);
        // consumer chain on side stream
        cudaStreamWaitEvent(R.s2, R.evNorm[b], 0);
        k_conv_ratio<<<HW2 / 256,        256, 0, R.s2>>>(w, bv, b);
        k_blend     <<<(8 * HW24) / 256, 256, 0, R.s2>>>(x1, x2, out, b);
    }
    // join side stream back into the captured stream
    cudaEventRecord(R.evBlendLast, R.s2);
    cudaStreamWaitEvent(0, R.evBlendLast, 0);
}